// round 4
// baseline (speedup 1.0000x reference)
#include <cuda_runtime.h>

// Conv2D 4096x4096 (fp32) * 16x16 filter, VALID -> 4081x4081, + bias[0].
// y[i,j] = sum_{a,b} x[i+a, j+b] * w[a,b]  (cross-correlation, per JAX semantics)

#define H  4096
#define W  4096
#define KH 16
#define KW 16
#define OH (H - KH + 1)   // 4081
#define OW (W - KW + 1)   // 4081

#define BW 128            // output cols per block
#define BH 32             // output rows per block
#define TR 16             // output rows per thread (1 col per thread)
#define IN_ROWS (BH + KH - 1)   // 47
#define PITCH   144             // padded smem row pitch (floats, mult of 4)

__global__ __launch_bounds__(256)
void Conv2D_87058987090635_kernel(const float* __restrict__ x,
                                  const float* __restrict__ w,
                                  const float* __restrict__ bias,
                                  float* __restrict__ out)
{
    __shared__ float xs[IN_ROWS * PITCH];   // 47*144*4 = 27072 B
    __shared__ float ws[KH * KW];           // 1 KB

    const int tx  = threadIdx.x;            // 0..127 -> output col within tile
    const int ty  = threadIdx.y;            // 0..1   -> row-group (16 rows each)
    const int tid = ty * 128 + tx;

    const int tile_col = blockIdx.x * BW;
    const int tile_row = blockIdx.y * BH;

    // --- load filter to smem (exactly 256 threads, 256 weights) ---
    ws[tid] = w[tid];

    // --- fill input tile: IN_ROWS x 143 (padded to 144) via float4 ---
    const int NV = IN_ROWS * (PITCH / 4);   // 47 * 36 = 1692 float4 slots
    for (int s = tid; s < NV; s += 256) {
        const int k  = s / (PITCH / 4);
        const int c4 = (s % (PITCH / 4)) * 4;
        const int gr = tile_row + k;
        const int gc = tile_col + c4;
        float4 v = make_float4(0.f, 0.f, 0.f, 0.f);
        if (gr < H) {
            const float* row = x + (size_t)gr * W;
            if (gc + 3 < W) {
                v = *reinterpret_cast<const float4*>(row + gc);
            } else {
                if (gc + 0 < W) v.x = row[gc + 0];
                if (gc + 1 < W) v.y = row[gc + 1];
                if (gc + 2 < W) v.z = row[gc + 2];
            }
        }
        *reinterpret_cast<float4*>(&xs[k * PITCH + c4]) = v;
    }
    __syncthreads();

    // --- compute: each thread = 16-row x 1-col output strip ---
    const int ry0 = ty * TR;

    float acc[TR];
    #pragma unroll
    for (int r = 0; r < TR; ++r) acc[r] = 0.f;

    for (int b = 0; b < KW; ++b) {
        // weights for this filter column (smem broadcast)
        float wv[KH];
        #pragma unroll
        for (int a = 0; a < KH; ++a) wv[a] = ws[a * KW + b];

        // input column window: rows ry0 .. ry0+30 at col (tx + b)
        float col[TR + KH - 1];
        #pragma unroll
        for (int k = 0; k < TR + KH - 1; ++k)
            col[k] = xs[(ry0 + k) * PITCH + tx + b];

        // 256 FMAs, 16 independent accumulation chains
        #pragma unroll
        for (int a = 0; a < KH; ++a) {
            #pragma unroll
            for (int r = 0; r < TR; ++r)
                acc[r] = fmaf(col[a + r], wv[a], acc[r]);
        }
    }

    const float b0 = bias[0];
    const int ocol = tile_col + tx;
    #pragma unroll
    for (int r = 0; r < TR; ++r) {
        const int orow = tile_row + ry0 + r;
        if (orow < OH && ocol < OW)
            out[(size_t)orow * OW + ocol] = acc[r] + b0;
    }
}

extern "C" void kernel_launch(void* const* d_in, const int* in_sizes, int n_in,
                              void* d_out, int out_size)
{
    const float* x    = (const float*)d_in[0];   // 4096*4096
    const float* w    = (const float*)d_in[1];   // 16*16
    const float* bias = (const float*)d_in[2];   // 1
    float* out        = (float*)d_out;           // 4081*4081

    dim3 block(128, 2);
    dim3 grid((OW + BW - 1) / BW,   // 32
              (OH + BH - 1) / BH);  // 128
    Conv2D_87058987090635_kernel<<<grid, block>>>(x, w, bias, out);
}